// round 1
// baseline (speedup 1.0000x reference)
#include <cuda_runtime.h>
#include <cuda_bf16.h>
#include <cstdint>

typedef __nv_bfloat16 bf16;

// Problem constants
// B=2, T=2048, E=2048, V=4096, NH=8, KD=256, HD=512
#define SZ_TE ((size_t)4096*2048)   // (B*T, E)
#define SZ_TV ((size_t)4096*4096)   // (B*T, V)
#define SZ_E2 ((size_t)2048*2048)   // wq/wk
#define SZ_VE ((size_t)4096*2048)   // wv/wg
#define SZ_EV ((size_t)2048*4096)   // wout
#define SZ_S  ((size_t)16*2048*2048)

// ---- scratch (static device memory; zero-initialized at module load) ----
__device__ bf16  g_xhi[SZ_TE],  g_xlo[SZ_TE];
__device__ bf16  g_wqhi[SZ_E2], g_wqlo[SZ_E2];
__device__ bf16  g_wkhi[SZ_E2], g_wklo[SZ_E2];
__device__ bf16  g_wvhi[SZ_VE], g_wvlo[SZ_VE];
__device__ bf16  g_wghi[SZ_VE], g_wglo[SZ_VE];
__device__ bf16  g_wohi[SZ_EV], g_wolo[SZ_EV];
__device__ float g_qf[SZ_TE],   g_kf[SZ_TE];
__device__ bf16  g_qrhi[SZ_TE], g_qrlo[SZ_TE];
__device__ bf16  g_krhi[SZ_TE], g_krlo[SZ_TE];
__device__ bf16  g_vhi[SZ_TV],  g_vlo[SZ_TV];
__device__ float g_gf[SZ_TV];
__device__ bf16  g_shi[SZ_S],   g_slo[SZ_S];
__device__ float g_invd[16*2048];
__device__ float g_of[SZ_TV];
__device__ bf16  g_gahi[SZ_TV], g_galo[SZ_TV];

// ---- helpers ----
__device__ __forceinline__ void split_store(bf16* hi, bf16* lo, long idx, float v) {
    bf16 h = __float2bfloat16(v);
    hi[idx] = h;
    lo[idx] = __float2bfloat16(v - __bfloat162float(h));
}

#define MMA(d, a, b) asm volatile( \
    "mma.sync.aligned.m16n8k16.row.col.f32.bf16.bf16.f32 " \
    "{%0,%1,%2,%3}, {%4,%5,%6,%7}, {%8,%9}, {%0,%1,%2,%3};\n" \
    : "+f"((d)[0]), "+f"((d)[1]), "+f"((d)[2]), "+f"((d)[3]) \
    : "r"((a)[0]), "r"((a)[1]), "r"((a)[2]), "r"((a)[3]), "r"((b)[0]), "r"((b)[1]))

// ---- generic bf16x3 GEMM: C[M,N] = A[M,K] * op(B), fp32 accumulate ----
// bLayout==0: B is (N,K) row-major (i.e., C = A * B^T)
// bLayout==1: B is (K,N) row-major (i.e., C = A * B)
// epi: 0 = fp32 store, 1 = split store, 2 = *decay_mask then split store,
//      3 = *inv[row] then fp32 store
struct GP {
    const bf16 *Ahi, *Alo, *Bhi, *Blo;
    float* Cf; bf16 *Chi, *Clo;
    const float* dm; const float* inv;
    long aSb, aSh, bSb, bSh, cSb, cSh;   // batch offsets: off = b*Sb + h*Sh (b=z/8, h=z%8)
    int lda, ldb, ldc;
    int M, N, K;
    int bLayout, epi, causalSkip, causalK;
};

__global__ void __launch_bounds__(256, 1) gemm_bf16x3(const GP p) {
    const int z    = blockIdx.z;
    const int bb   = z >> 3, hh = z & 7;
    const int row0 = blockIdx.y * 128;
    const int col0 = blockIdx.x * 128;
    if (p.causalSkip && col0 > row0 + 127) return;   // strictly-upper tile: never needed

    const bf16* __restrict__ Ahi = p.Ahi + (long)bb * p.aSb + (long)hh * p.aSh;
    const bf16* __restrict__ Alo = p.Alo + (long)bb * p.aSb + (long)hh * p.aSh;
    const bf16* __restrict__ Bhi = p.Bhi + (long)bb * p.bSb + (long)hh * p.bSh;
    const bf16* __restrict__ Blo = p.Blo + (long)bb * p.bSb + (long)hh * p.bSh;

    __shared__ bf16 sA[2][128][40];   // stride 40 bf16 -> conflict-free fragment loads
    __shared__ bf16 sB[2][128][40];

    const int tid  = threadIdx.x;
    const int lane = tid & 31;
    const int wid  = tid >> 5;
    const int wm   = (wid >> 2) * 64;   // 2x4 warp grid, 64x32 warp tile
    const int wn   = (wid & 3) * 32;

    float acc[4][4][4];
    #pragma unroll
    for (int i = 0; i < 4; i++)
        #pragma unroll
        for (int j = 0; j < 4; j++)
            #pragma unroll
            for (int e = 0; e < 4; e++) acc[i][j][e] = 0.f;

    const int Keff = p.causalK ? min(p.K, row0 + 128) : p.K;

    for (int k0 = 0; k0 < Keff; k0 += 32) {
        {   // A tile: (128 x 32) from row-major A
            const int tr = tid >> 3;
            const int tc = (tid & 7) << 2;
            #pragma unroll
            for (int i = 0; i < 4; i++) {
                const int r = tr + i * 32;
                const long off = (long)(row0 + r) * p.lda + k0 + tc;
                *(uint2*)&sA[0][r][tc] = *(const uint2*)(Ahi + off);
                *(uint2*)&sA[1][r][tc] = *(const uint2*)(Alo + off);
            }
        }
        if (p.bLayout == 0) {   // B (N,K) row-major
            const int tr = tid >> 3;
            const int tc = (tid & 7) << 2;
            #pragma unroll
            for (int i = 0; i < 4; i++) {
                const int r = tr + i * 32;
                const long off = (long)(col0 + r) * p.ldb + k0 + tc;
                *(uint2*)&sB[0][r][tc] = *(const uint2*)(Bhi + off);
                *(uint2*)&sB[1][r][tc] = *(const uint2*)(Blo + off);
            }
        } else {                // B (K,N) row-major -> transpose into smem
            const int kw = tid >> 5;
            const int ng = (tid & 31) << 2;
            #pragma unroll
            for (int i = 0; i < 4; i++) {
                const int kk2 = kw + i * 8;
                const long off = (long)(k0 + kk2) * p.ldb + col0 + ng;
                uint2 vh = *(const uint2*)(Bhi + off);
                uint2 vl = *(const uint2*)(Blo + off);
                bf16 th[4], tl[4];
                *(uint2*)th = vh; *(uint2*)tl = vl;
                #pragma unroll
                for (int j = 0; j < 4; j++) {
                    sB[0][ng + j][kk2] = th[j];
                    sB[1][ng + j][kk2] = tl[j];
                }
            }
        }
        __syncthreads();

        #pragma unroll
        for (int kk = 0; kk < 32; kk += 16) {
            unsigned ah[4][4], al[4][4], bh[4][2], bl[4][2];
            const int c0 = kk + ((lane & 3) << 1);
            #pragma unroll
            for (int fm = 0; fm < 4; fm++) {
                const int r0 = wm + fm * 16 + (lane >> 2);
                ah[fm][0] = *(const unsigned*)&sA[0][r0][c0];
                ah[fm][1] = *(const unsigned*)&sA[0][r0 + 8][c0];
                ah[fm][2] = *(const unsigned*)&sA[0][r0][c0 + 8];
                ah[fm][3] = *(const unsigned*)&sA[0][r0 + 8][c0 + 8];
                al[fm][0] = *(const unsigned*)&sA[1][r0][c0];
                al[fm][1] = *(const unsigned*)&sA[1][r0 + 8][c0];
                al[fm][2] = *(const unsigned*)&sA[1][r0][c0 + 8];
                al[fm][3] = *(const unsigned*)&sA[1][r0 + 8][c0 + 8];
            }
            #pragma unroll
            for (int fn = 0; fn < 4; fn++) {
                const int n0 = wn + fn * 8 + (lane >> 2);
                bh[fn][0] = *(const unsigned*)&sB[0][n0][c0];
                bh[fn][1] = *(const unsigned*)&sB[0][n0][c0 + 8];
                bl[fn][0] = *(const unsigned*)&sB[1][n0][c0];
                bl[fn][1] = *(const unsigned*)&sB[1][n0][c0 + 8];
            }
            #pragma unroll
            for (int fm = 0; fm < 4; fm++)
                #pragma unroll
                for (int fn = 0; fn < 4; fn++) {
                    MMA(acc[fm][fn], ah[fm], bh[fn]);
                    MMA(acc[fm][fn], ah[fm], bl[fn]);
                    MMA(acc[fm][fn], al[fm], bh[fn]);
                }
        }
        __syncthreads();
    }

    // epilogue
    const long cb = (long)bb * p.cSb + (long)hh * p.cSh;
    const float* dmh = p.dm ? (p.dm + (long)hh * (long)p.M * p.N) : (const float*)0;
    #pragma unroll
    for (int fm = 0; fm < 4; fm++) {
        #pragma unroll
        for (int fn = 0; fn < 4; fn++) {
            #pragma unroll
            for (int e = 0; e < 4; e++) {
                const int r = row0 + wm + fm * 16 + (lane >> 2) + ((e >> 1) << 3);
                const int c = col0 + wn + fn * 8 + ((lane & 3) << 1) + (e & 1);
                float v = acc[fm][fn][e];
                const long ci = cb + (long)r * p.ldc + c;
                if (p.epi == 0) {
                    p.Cf[ci] = v;
                } else if (p.epi == 1) {
                    split_store(p.Chi, p.Clo, ci, v);
                } else if (p.epi == 2) {
                    v *= dmh[(long)r * p.N + c];
                    split_store(p.Chi, p.Clo, ci, v);
                } else {
                    v *= p.inv[(long)z * p.M + r];
                    p.Cf[ci] = v;
                }
            }
        }
    }
}

// ---- elementwise kernels ----
__global__ void split_kernel(const float* __restrict__ x, bf16* __restrict__ hi,
                             bf16* __restrict__ lo, long n) {
    long i = (long)blockIdx.x * blockDim.x + threadIdx.x;
    const long stride = (long)gridDim.x * blockDim.x;
    for (; i < n; i += stride) split_store(hi, lo, i, x[i]);
}

// rotary for q and k (k scaled by KD^-0.5 = 1/16); one thread per element pair
__global__ void rotary_kernel(const float* __restrict__ q, const float* __restrict__ k,
                              const float* __restrict__ sinp, const float* __restrict__ cosp,
                              bf16* __restrict__ qhi, bf16* __restrict__ qlo,
                              bf16* __restrict__ khi, bf16* __restrict__ klo) {
    const long pidx = (long)blockIdx.x * blockDim.x + threadIdx.x;
    if (pidx >= (long)4096 * 1024) return;
    const long base = pidx * 2;              // flat index into (B*T, E)
    const int  col  = (int)(base & 2047);    // E = 2048
    const long bt   = base >> 11;
    const int  t    = (int)(bt & 2047);      // T = 2048
    const int  dd   = col & 255;             // KD = 256
    const float c0 = cosp[t * 256 + dd],     s0 = sinp[t * 256 + dd];
    const float c1 = cosp[t * 256 + dd + 1], s1 = sinp[t * 256 + dd + 1];
    float x0 = q[base], x1 = q[base + 1];
    split_store(qhi, qlo, base,     x0 * c0 - x1 * s0);
    split_store(qhi, qlo, base + 1, x1 * c1 + x0 * s1);
    x0 = k[base]; x1 = k[base + 1];
    split_store(khi, klo, base,     0.0625f * (x0 * c0 - x1 * s0));
    split_store(khi, klo, base + 1, 0.0625f * (x1 * c1 + x0 * s1));
}

// per-row (z=bh, t): inv = 1/max(|sum_{s<=t} S|, 1)
__global__ void rowsum_kernel(const bf16* __restrict__ Shi, const bf16* __restrict__ Slo,
                              float* __restrict__ inv) {
    const int t = blockIdx.x, z = blockIdx.y;
    const long rb = ((long)z * 2048 + t) * 2048;
    float s = 0.f;
    for (int i = threadIdx.x; i <= t; i += 256)
        s += __bfloat162float(Shi[rb + i]) + __bfloat162float(Slo[rb + i]);
    #pragma unroll
    for (int o = 16; o; o >>= 1) s += __shfl_down_sync(0xffffffffu, s, o);
    __shared__ float red[8];
    if ((threadIdx.x & 31) == 0) red[threadIdx.x >> 5] = s;
    __syncthreads();
    if (threadIdx.x < 8) {
        float v = red[threadIdx.x];
        #pragma unroll
        for (int o = 4; o; o >>= 1) v += __shfl_down_sync(0xffu, v, o);
        if (threadIdx.x == 0) inv[(long)z * 2048 + t] = 1.0f / fmaxf(fabsf(v), 1.0f);
    }
}

// per (bt,h): RMS norm over HD=512, silu gate, split store
__global__ void gate_kernel(const float* __restrict__ o, const float* __restrict__ g,
                            bf16* __restrict__ ghi, bf16* __restrict__ glo) {
    const int blk = blockIdx.x;           // bt*8 + h
    const int h   = blk & 7;
    const long bt = blk >> 3;
    const long base = bt * 4096 + h * 512;
    const int tid = threadIdx.x;          // 128 threads, 4 elems each
    float4 x = *(const float4*)(o + base + tid * 4);
    float ss = x.x * x.x + x.y * x.y + x.z * x.z + x.w * x.w;
    #pragma unroll
    for (int off = 16; off; off >>= 1) ss += __shfl_down_sync(0xffffffffu, ss, off);
    __shared__ float ws[4];
    __shared__ float tot;
    if ((tid & 31) == 0) ws[tid >> 5] = ss;
    __syncthreads();
    if (tid == 0) tot = ws[0] + ws[1] + ws[2] + ws[3];
    __syncthreads();
    const float r = rsqrtf(tot * (1.0f / 512.0f) + 1e-6f);
    float4 gv = *(const float4*)(g + base + tid * 4);
    const float xv[4] = {x.x, x.y, x.z, x.w};
    const float gg[4] = {gv.x, gv.y, gv.z, gv.w};
    #pragma unroll
    for (int j = 0; j < 4; j++) {
        const float sig = 1.0f / (1.0f + expf(-gg[j]));
        const float val = gg[j] * sig * xv[j] * r;
        split_store(ghi, glo, base + tid * 4 + j, val);
    }
}

// ---- host side ----
static void run_gemm(const bf16* Ahi, const bf16* Alo, int lda, long aSb, long aSh,
                     const bf16* Bhi, const bf16* Blo, int ldb, long bSb, long bSh, int bLayout,
                     int M, int N, int K, int batches, int epi,
                     float* Cf, bf16* Chi, bf16* Clo, int ldc, long cSb, long cSh,
                     const float* dm, const float* inv, int causalSkip, int causalK) {
    GP p;
    p.Ahi = Ahi; p.Alo = Alo; p.Bhi = Bhi; p.Blo = Blo;
    p.Cf = Cf; p.Chi = Chi; p.Clo = Clo; p.dm = dm; p.inv = inv;
    p.aSb = aSb; p.aSh = aSh; p.bSb = bSb; p.bSh = bSh; p.cSb = cSb; p.cSh = cSh;
    p.lda = lda; p.ldb = ldb; p.ldc = ldc;
    p.M = M; p.N = N; p.K = K;
    p.bLayout = bLayout; p.epi = epi; p.causalSkip = causalSkip; p.causalK = causalK;
    dim3 grid(N / 128, M / 128, batches);
    gemm_bf16x3<<<grid, 256>>>(p);
}

#define GETP(ptr, sym, T) T* ptr; { void* _p = 0; cudaGetSymbolAddress(&_p, sym); ptr = (T*)_p; }

extern "C" void kernel_launch(void* const* d_in, const int* in_sizes, int n_in,
                              void* d_out, int out_size) {
    const float* hs   = (const float*)d_in[0];
    const float* sinp = (const float*)d_in[1];
    const float* cosp = (const float*)d_in[2];
    const float* dm   = (const float*)d_in[3];
    const float* wq   = (const float*)d_in[4];
    const float* wk   = (const float*)d_in[5];
    const float* wv   = (const float*)d_in[6];
    const float* wg   = (const float*)d_in[7];
    const float* wo   = (const float*)d_in[8];
    float* out = (float*)d_out;

    GETP(xhi,  g_xhi,  bf16)  GETP(xlo,  g_xlo,  bf16)
    GETP(wqhi, g_wqhi, bf16)  GETP(wqlo, g_wqlo, bf16)
    GETP(wkhi, g_wkhi, bf16)  GETP(wklo, g_wklo, bf16)
    GETP(wvhi, g_wvhi, bf16)  GETP(wvlo, g_wvlo, bf16)
    GETP(wghi, g_wghi, bf16)  GETP(wglo, g_wglo, bf16)
    GETP(wohi, g_wohi, bf16)  GETP(wolo, g_wolo, bf16)
    GETP(qf,   g_qf,   float) GETP(kf,   g_kf,   float)
    GETP(qrhi, g_qrhi, bf16)  GETP(qrlo, g_qrlo, bf16)
    GETP(krhi, g_krhi, bf16)  GETP(krlo, g_krlo, bf16)
    GETP(vhi,  g_vhi,  bf16)  GETP(vlo,  g_vlo,  bf16)
    GETP(gf,   g_gf,   float)
    GETP(shi,  g_shi,  bf16)  GETP(slo,  g_slo,  bf16)
    GETP(invp, g_invd, float)
    GETP(of,   g_of,   float)
    GETP(gahi, g_gahi, bf16)  GETP(galo, g_galo, bf16)

    // 1) split fp32 inputs into bf16 hi/lo pairs
    split_kernel<<<2048, 256>>>(hs, xhi,  xlo,  (long)4096 * 2048);
    split_kernel<<<2048, 256>>>(wq, wqhi, wqlo, (long)2048 * 2048);
    split_kernel<<<2048, 256>>>(wk, wkhi, wklo, (long)2048 * 2048);
    split_kernel<<<2048, 256>>>(wv, wvhi, wvlo, (long)4096 * 2048);
    split_kernel<<<2048, 256>>>(wg, wghi, wglo, (long)4096 * 2048);
    split_kernel<<<2048, 256>>>(wo, wohi, wolo, (long)2048 * 4096);

    // 2) projections: q,k -> fp32 (rotary consumes), v -> split, g -> fp32
    run_gemm(xhi, xlo, 2048, 0, 0, wqhi, wqlo, 2048, 0, 0, 0,
             4096, 2048, 2048, 1, 0, qf, 0, 0, 2048, 0, 0, 0, 0, 0, 0);
    run_gemm(xhi, xlo, 2048, 0, 0, wkhi, wklo, 2048, 0, 0, 0,
             4096, 2048, 2048, 1, 0, kf, 0, 0, 2048, 0, 0, 0, 0, 0, 0);
    run_gemm(xhi, xlo, 2048, 0, 0, wvhi, wvlo, 2048, 0, 0, 0,
             4096, 4096, 2048, 1, 1, 0, vhi, vlo, 4096, 0, 0, 0, 0, 0, 0);
    run_gemm(xhi, xlo, 2048, 0, 0, wghi, wglo, 2048, 0, 0, 0,
             4096, 4096, 2048, 1, 0, gf, 0, 0, 4096, 0, 0, 0, 0, 0, 0);

    // 3) rotary + k-scaling, write split qr/kr
    rotary_kernel<<<16384, 256>>>(qf, kf, sinp, cosp, qrhi, qrlo, krhi, krlo);

    // 4) S = (qr . kr^T) * dm, batched over 16 (b,h); skip strictly-upper tiles
    run_gemm(qrhi, qrlo, 2048, (long)2048 * 2048, 256,
             krhi, krlo, 2048, (long)2048 * 2048, 256, 0,
             2048, 2048, 256, 16, 2, 0, shi, slo, 2048,
             (long)8 * 2048 * 2048, (long)2048 * 2048, dm, 0, 1, 0);

    // 5) inv = 1/max(|rowsum|,1)
    rowsum_kernel<<<dim3(2048, 16), 256>>>(shi, slo, invp);

    // 6) O = inv * (S @ V), K limited causally; C written in (b,t,h*HD+d) layout
    run_gemm(shi, slo, 2048, (long)8 * 2048 * 2048, (long)2048 * 2048,
             vhi, vlo, 4096, (long)2048 * 4096, 512, 1,
             2048, 512, 2048, 16, 3, of, 0, 0, 4096,
             (long)2048 * 4096, 512, 0, invp, 0, 1);

    // 7) per-head RMS norm + silu(g) gating -> split gated
    gate_kernel<<<32768, 128>>>(of, gf, gahi, galo);

    // 8) output projection -> d_out fp32
    run_gemm(gahi, galo, 4096, 0, 0, wohi, wolo, 4096, 0, 0, 0,
             4096, 2048, 4096, 1, 0, out, 0, 0, 2048, 0, 0, 0, 0, 0, 0);
}

// round 2
// speedup vs baseline: 1.3997x; 1.3997x over previous
#include <cuda_runtime.h>
#include <cuda_bf16.h>
#include <cstdint>

typedef __nv_bfloat16 bf16;

// B=2, T=2048, E=2048, V=4096, NH=8, KD=256, HD=512
#define SZ_TE ((size_t)4096*2048)
#define SZ_TV ((size_t)4096*4096)
#define SZ_E2 ((size_t)2048*2048)
#define SZ_VE ((size_t)4096*2048)
#define SZ_EV ((size_t)2048*4096)
#define SZ_S  ((size_t)16*2048*2048)

// ---- scratch ----
__device__ bf16  g_xhi[SZ_TE],  g_xlo[SZ_TE];
__device__ bf16  g_wqhi[SZ_E2], g_wqlo[SZ_E2];
__device__ bf16  g_wkhi[SZ_E2], g_wklo[SZ_E2];
__device__ bf16  g_wvhi[SZ_VE], g_wvlo[SZ_VE];
__device__ bf16  g_wghi[SZ_VE], g_wglo[SZ_VE];
__device__ bf16  g_wohi[SZ_EV], g_wolo[SZ_EV];
__device__ bf16  g_qrhi[SZ_TE], g_qrlo[SZ_TE];
__device__ bf16  g_krhi[SZ_TE], g_krlo[SZ_TE];
__device__ bf16  g_vthi[SZ_TV], g_vtlo[SZ_TV];   // v transposed: per b, (V rows, T cols)
__device__ float g_gf[SZ_TV];
__device__ bf16  g_shi[SZ_S],   g_slo[SZ_S];
__device__ float g_invd[16*2048];
__device__ float g_of[SZ_TV];
__device__ bf16  g_gahi[SZ_TV], g_galo[SZ_TV];

// ---- helpers ----
__device__ __forceinline__ void split_store(bf16* hi, bf16* lo, long idx, float v) {
    bf16 h = __float2bfloat16(v);
    hi[idx] = h;
    lo[idx] = __float2bfloat16(v - __bfloat162float(h));
}

__device__ __forceinline__ void cp16(uint32_t dst, const void* src) {
    asm volatile("cp.async.cg.shared.global [%0], [%1], 16;\n" :: "r"(dst), "l"(src));
}

#define LDSM4(R, addr) asm volatile( \
    "ldmatrix.sync.aligned.m8n8.x4.shared.b16 {%0,%1,%2,%3}, [%4];\n" \
    : "=r"((R)[0]), "=r"((R)[1]), "=r"((R)[2]), "=r"((R)[3]) : "r"(addr))

#define MMA(d, a, b) asm volatile( \
    "mma.sync.aligned.m16n8k16.row.col.f32.bf16.bf16.f32 " \
    "{%0,%1,%2,%3}, {%4,%5,%6,%7}, {%8,%9}, {%0,%1,%2,%3};\n" \
    : "+f"((d)[0]), "+f"((d)[1]), "+f"((d)[2]), "+f"((d)[3]) \
    : "r"((a)[0]), "r"((a)[1]), "r"((a)[2]), "r"((a)[3]), "r"((b)[0]), "r"((b)[1]))

// ---- generic bf16x3 GEMM: C[M,N] = A[M,K] * B^T, B is (N,K) row-major ----
// epi: 0 = fp32 store, 1 = split store, 2 = *decay_mask then split store,
//      3 = *inv[row] then fp32 store, 4 = rotary(+scale) then split store
struct GP {
    const bf16 *Ahi, *Alo, *Bhi, *Blo;
    float* Cf; bf16 *Chi, *Clo;
    const float* dm; const float* inv; const float* sinp; const float* cosp;
    long aSb, aSh, bSb, bSh, cSb, cSh;   // off = bb*Sb + hh*Sh (bb=z>>3, hh=z&7)
    int lda, ldb, ldc;
    int M, N, K;
    int epi, causalSkip, causalK;
    float scale;
};

#define ST_ELEMS 20480            // per-stage smem elems: 4 comps * 128 * 40
#define SMEM_BYTES (3 * ST_ELEMS * 2)

__global__ void __launch_bounds__(256, 1) gemm_bf16x3(const __grid_constant__ GP p) {
    extern __shared__ __align__(16) bf16 smem[];
    const int z    = blockIdx.z;
    const int bb   = z >> 3, hh = z & 7;
    const int row0 = blockIdx.y * 128;
    const int col0 = blockIdx.x * 128;
    if (p.causalSkip && col0 > row0) return;   // strictly-upper tile

    const bf16* __restrict__ Ahi = p.Ahi + (long)bb * p.aSb + (long)hh * p.aSh;
    const bf16* __restrict__ Alo = p.Alo + (long)bb * p.aSb + (long)hh * p.aSh;
    const bf16* __restrict__ Bhi = p.Bhi + (long)bb * p.bSb + (long)hh * p.bSh;
    const bf16* __restrict__ Blo = p.Blo + (long)bb * p.bSb + (long)hh * p.bSh;

    const int tid  = threadIdx.x;
    const int lane = tid & 31;
    const int wid  = tid >> 5;
    const int wm   = (wid >> 2) * 64;
    const int wn   = (wid & 3) * 32;
    const uint32_t sbase = (uint32_t)__cvta_generic_to_shared(smem);

    const int Keff = p.causalK ? min(p.K, row0 + 128) : p.K;
    const int nk   = Keff >> 5;

    float acc[4][4][4];
    #pragma unroll
    for (int i = 0; i < 4; i++)
        #pragma unroll
        for (int j = 0; j < 4; j++)
            #pragma unroll
            for (int e = 0; e < 4; e++) acc[i][j][e] = 0.f;

    auto issue = [&](int it) {
        if (it < nk) {
            const int k0 = it << 5;
            const int st = (it % 3) * ST_ELEMS;
            #pragma unroll
            for (int ci = 0; ci < 2; ci++) {
                const int chunk = tid + ci * 256;       // 0..511
                const int row = chunk >> 2;             // 0..127
                const int cc  = (chunk & 3) << 3;       // bf16 col offset
                const long aoff = (long)(row0 + row) * p.lda + k0 + cc;
                const long boff = (long)(col0 + row) * p.ldb + k0 + cc;
                const uint32_t d0 = sbase + (uint32_t)(st + row * 40 + cc) * 2;
                cp16(d0,             Ahi + aoff);
                cp16(d0 +  5120 * 2, Alo + aoff);
                cp16(d0 + 10240 * 2, Bhi + boff);
                cp16(d0 + 15360 * 2, Blo + boff);
            }
        }
        asm volatile("cp.async.commit_group;\n");
    };

    issue(0); issue(1); issue(2);

    for (int it = 0; it < nk; it++) {
        asm volatile("cp.async.wait_group 2;\n");
        __syncthreads();
        const int st = (it % 3) * ST_ELEMS;

        #pragma unroll
        for (int kk = 0; kk < 32; kk += 16) {
            uint32_t ah[4][4], al[4][4], bh[2][4], bl[2][4];
            const int mat = lane >> 3, t7 = lane & 7;
            const int arow = ((mat & 1) << 3) + t7;
            const int acol = (mat >> 1) << 3;
            #pragma unroll
            for (int fm = 0; fm < 4; fm++) {
                const uint32_t ad = sbase +
                    (uint32_t)(st + (wm + fm * 16 + arow) * 40 + kk + acol) * 2;
                LDSM4(ah[fm], ad);
                LDSM4(al[fm], ad + 5120 * 2);
            }
            const int brow = ((mat >> 1) << 3) + t7;
            const int bcol = (mat & 1) << 3;
            #pragma unroll
            for (int fp = 0; fp < 2; fp++) {
                const uint32_t bd = sbase +
                    (uint32_t)(st + 10240 + (wn + fp * 16 + brow) * 40 + kk + bcol) * 2;
                LDSM4(bh[fp], bd);
                LDSM4(bl[fp], bd + 5120 * 2);
            }
            #pragma unroll
            for (int fm = 0; fm < 4; fm++)
                #pragma unroll
                for (int fn = 0; fn < 4; fn++) {
                    uint32_t* bhp = &bh[fn >> 1][(fn & 1) * 2];
                    uint32_t* blp = &bl[fn >> 1][(fn & 1) * 2];
                    MMA(acc[fm][fn], ah[fm], bhp);
                    MMA(acc[fm][fn], ah[fm], blp);
                    MMA(acc[fm][fn], al[fm], bhp);
                }
        }
        __syncthreads();
        issue(it + 3);
    }

    // epilogue (pair-based: x0 at even col c, x1 at c+1)
    const long cb = (long)bb * p.cSb + (long)hh * p.cSh;
    const float* dmh = p.dm ? (p.dm + (long)hh * (long)p.M * p.N) : (const float*)0;
    #pragma unroll
    for (int fm = 0; fm < 4; fm++)
        #pragma unroll
        for (int fn = 0; fn < 4; fn++)
            #pragma unroll
            for (int half = 0; half < 2; half++) {
                const int r = row0 + wm + fm * 16 + (lane >> 2) + half * 8;
                const int c = col0 + wn + fn * 8 + ((lane & 3) << 1);
                float x0 = acc[fm][fn][half * 2];
                float x1 = acc[fm][fn][half * 2 + 1];
                const long ci = cb + (long)r * p.ldc + c;
                if (p.epi == 0) {
                    p.Cf[ci] = x0; p.Cf[ci + 1] = x1;
                } else if (p.epi == 1) {
                    split_store(p.Chi, p.Clo, ci, x0);
                    split_store(p.Chi, p.Clo, ci + 1, x1);
                } else if (p.epi == 2) {
                    x0 *= dmh[(long)r * p.N + c];
                    x1 *= dmh[(long)r * p.N + c + 1];
                    split_store(p.Chi, p.Clo, ci, x0);
                    split_store(p.Chi, p.Clo, ci + 1, x1);
                } else if (p.epi == 3) {
                    const float iv = p.inv[(long)z * p.M + r];
                    p.Cf[ci] = x0 * iv; p.Cf[ci + 1] = x1 * iv;
                } else {   // rotary (+ optional scale), split store
                    const int t = r & 2047, dd = c & 255;
                    const float c0 = p.cosp[t * 256 + dd],     s0 = p.sinp[t * 256 + dd];
                    const float c1 = p.cosp[t * 256 + dd + 1], s1 = p.sinp[t * 256 + dd + 1];
                    const float y0 = (x0 * c0 - x1 * s0) * p.scale;
                    const float y1 = (x1 * c1 + x0 * s1) * p.scale;
                    split_store(p.Chi, p.Clo, ci, y0);
                    split_store(p.Chi, p.Clo, ci + 1, y1);
                }
            }
}

// ---- elementwise kernels ----
__global__ void split_kernel(const float* __restrict__ x, bf16* __restrict__ hi,
                             bf16* __restrict__ lo, long n) {
    long i = (long)blockIdx.x * blockDim.x + threadIdx.x;
    const long stride = (long)gridDim.x * blockDim.x;
    for (; i < n; i += stride) split_store(hi, lo, i, x[i]);
}

__global__ void rowsum_kernel(const bf16* __restrict__ Shi, const bf16* __restrict__ Slo,
                              float* __restrict__ inv) {
    const int t = blockIdx.x, z = blockIdx.y;
    const long rb = ((long)z * 2048 + t) * 2048;
    float s = 0.f;
    for (int i = threadIdx.x; i <= t; i += 256)
        s += __bfloat162float(Shi[rb + i]) + __bfloat162float(Slo[rb + i]);
    #pragma unroll
    for (int o = 16; o; o >>= 1) s += __shfl_down_sync(0xffffffffu, s, o);
    __shared__ float red[8];
    if ((threadIdx.x & 31) == 0) red[threadIdx.x >> 5] = s;
    __syncthreads();
    if (threadIdx.x < 8) {
        float v = red[threadIdx.x];
        #pragma unroll
        for (int o = 4; o; o >>= 1) v += __shfl_down_sync(0xffu, v, o);
        if (threadIdx.x == 0) inv[(long)z * 2048 + t] = 1.0f / fmaxf(fabsf(v), 1.0f);
    }
}

__global__ void gate_kernel(const float* __restrict__ o, const float* __restrict__ g,
                            bf16* __restrict__ ghi, bf16* __restrict__ glo) {
    const int blk = blockIdx.x;           // bt*8 + h
    const int h   = blk & 7;
    const long bt = blk >> 3;
    const long base = bt * 4096 + h * 512;
    const int tid = threadIdx.x;          // 128 threads, 4 elems each
    float4 x = *(const float4*)(o + base + tid * 4);
    float ss = x.x * x.x + x.y * x.y + x.z * x.z + x.w * x.w;
    #pragma unroll
    for (int off = 16; off; off >>= 1) ss += __shfl_down_sync(0xffffffffu, ss, off);
    __shared__ float ws[4];
    __shared__ float tot;
    if ((tid & 31) == 0) ws[tid >> 5] = ss;
    __syncthreads();
    if (tid == 0) tot = ws[0] + ws[1] + ws[2] + ws[3];
    __syncthreads();
    const float r = rsqrtf(tot * (1.0f / 512.0f) + 1e-6f);
    float4 gv = *(const float4*)(g + base + tid * 4);
    const float xv[4] = {x.x, x.y, x.z, x.w};
    const float gg[4] = {gv.x, gv.y, gv.z, gv.w};
    #pragma unroll
    for (int j = 0; j < 4; j++) {
        const float sig = 1.0f / (1.0f + expf(-gg[j]));
        const float val = gg[j] * sig * xv[j] * r;
        split_store(ghi, glo, base + tid * 4 + j, val);
    }
}

// ---- host side ----
static void run_gemm(const bf16* Ahi, const bf16* Alo, int lda, long aSb, long aSh,
                     const bf16* Bhi, const bf16* Blo, int ldb, long bSb, long bSh,
                     int M, int N, int K, int batches, int epi,
                     float* Cf, bf16* Chi, bf16* Clo, int ldc, long cSb, long cSh,
                     const float* dm, const float* inv,
                     const float* sinp, const float* cosp, float scale,
                     int causalSkip, int causalK) {
    GP p;
    p.Ahi = Ahi; p.Alo = Alo; p.Bhi = Bhi; p.Blo = Blo;
    p.Cf = Cf; p.Chi = Chi; p.Clo = Clo;
    p.dm = dm; p.inv = inv; p.sinp = sinp; p.cosp = cosp;
    p.aSb = aSb; p.aSh = aSh; p.bSb = bSb; p.bSh = bSh; p.cSb = cSb; p.cSh = cSh;
    p.lda = lda; p.ldb = ldb; p.ldc = ldc;
    p.M = M; p.N = N; p.K = K;
    p.epi = epi; p.causalSkip = causalSkip; p.causalK = causalK; p.scale = scale;
    dim3 grid(N / 128, M / 128, batches);
    gemm_bf16x3<<<grid, 256, SMEM_BYTES>>>(p);
}

#define GETP(ptr, sym, T) T* ptr; { void* _p = 0; cudaGetSymbolAddress(&_p, sym); ptr = (T*)_p; }

extern "C" void kernel_launch(void* const* d_in, const int* in_sizes, int n_in,
                              void* d_out, int out_size) {
    const float* hs   = (const float*)d_in[0];
    const float* sinp = (const float*)d_in[1];
    const float* cosp = (const float*)d_in[2];
    const float* dm   = (const float*)d_in[3];
    const float* wq   = (const float*)d_in[4];
    const float* wk   = (const float*)d_in[5];
    const float* wv   = (const float*)d_in[6];
    const float* wg   = (const float*)d_in[7];
    const float* wo   = (const float*)d_in[8];
    float* out = (float*)d_out;

    cudaFuncSetAttribute(gemm_bf16x3, cudaFuncAttributeMaxDynamicSharedMemorySize, SMEM_BYTES);

    GETP(xhi,  g_xhi,  bf16)  GETP(xlo,  g_xlo,  bf16)
    GETP(wqhi, g_wqhi, bf16)  GETP(wqlo, g_wqlo, bf16)
    GETP(wkhi, g_wkhi, bf16)  GETP(wklo, g_wklo, bf16)
    GETP(wvhi, g_wvhi, bf16)  GETP(wvlo, g_wvlo, bf16)
    GETP(wghi, g_wghi, bf16)  GETP(wglo, g_wglo, bf16)
    GETP(wohi, g_wohi, bf16)  GETP(wolo, g_wolo, bf16)
    GETP(qrhi, g_qrhi, bf16)  GETP(qrlo, g_qrlo, bf16)
    GETP(krhi, g_krhi, bf16)  GETP(krlo, g_krlo, bf16)
    GETP(vthi, g_vthi, bf16)  GETP(vtlo, g_vtlo, bf16)
    GETP(gf,   g_gf,   float)
    GETP(shi,  g_shi,  bf16)  GETP(slo,  g_slo,  bf16)
    GETP(invp, g_invd, float)
    GETP(of,   g_of,   float)
    GETP(gahi, g_gahi, bf16)  GETP(galo, g_galo, bf16)

    // 1) split fp32 inputs into bf16 hi/lo pairs
    split_kernel<<<2048, 256>>>(hs, xhi,  xlo,  (long)4096 * 2048);
    split_kernel<<<2048, 256>>>(wq, wqhi, wqlo, (long)2048 * 2048);
    split_kernel<<<2048, 256>>>(wk, wkhi, wklo, (long)2048 * 2048);
    split_kernel<<<2048, 256>>>(wv, wvhi, wvlo, (long)4096 * 2048);
    split_kernel<<<2048, 256>>>(wg, wghi, wglo, (long)4096 * 2048);
    split_kernel<<<2048, 256>>>(wo, wohi, wolo, (long)2048 * 4096);

    // 2) q/k projections with fused rotary (+ k scaling) -> split qr/kr
    run_gemm(xhi, xlo, 2048, 0, 0, wqhi, wqlo, 2048, 0, 0,
             4096, 2048, 2048, 1, 4, 0, qrhi, qrlo, 2048, 0, 0,
             0, 0, sinp, cosp, 1.0f, 0, 0);
    run_gemm(xhi, xlo, 2048, 0, 0, wkhi, wklo, 2048, 0, 0,
             4096, 2048, 2048, 1, 4, 0, krhi, krlo, 2048, 0, 0,
             0, 0, sinp, cosp, 0.0625f, 0, 0);

    // 3) vT = Wv @ x^T per batch: A=wv (V,E), B=x rows of batch b -> C (V, T)
    run_gemm(wvhi, wvlo, 2048, 0, 0, xhi, xlo, 2048, 0, (long)2048 * 2048,
             4096, 2048, 2048, 2, 1, 0, vthi, vtlo, 2048, 0, (long)4096 * 2048,
             0, 0, 0, 0, 1.0f, 0, 0);

    // 4) g projection -> fp32
    run_gemm(xhi, xlo, 2048, 0, 0, wghi, wglo, 2048, 0, 0,
             4096, 4096, 2048, 1, 0, gf, 0, 0, 4096, 0, 0,
             0, 0, 0, 0, 1.0f, 0, 0);

    // 5) S = (qr . kr^T) * dm, batched over 16 (b,h); skip strictly-upper tiles
    run_gemm(qrhi, qrlo, 2048, (long)2048 * 2048, 256,
             krhi, krlo, 2048, (long)2048 * 2048, 256,
             2048, 2048, 256, 16, 2, 0, shi, slo, 2048,
             (long)8 * 2048 * 2048, (long)2048 * 2048,
             dm, 0, 0, 0, 1.0f, 1, 0);

    // 6) inv = 1/max(|rowsum|,1)
    rowsum_kernel<<<dim3(2048, 16), 256>>>(shi, slo, invp);

    // 7) O = inv * (S @ vT^T), K causally limited; written as (b,t,h*HD+d)
    run_gemm(shi, slo, 2048, (long)8 * 2048 * 2048, (long)2048 * 2048,
             vthi, vtlo, 2048, (long)4096 * 2048, (long)512 * 2048,
             2048, 512, 2048, 16, 3, of, 0, 0, 4096,
             (long)2048 * 4096, 512,
             0, invp, 0, 0, 1.0f, 0, 1);

    // 8) per-head RMS norm + silu(g) gating -> split gated
    gate_kernel<<<32768, 128>>>(of, gf, gahi, galo);

    // 9) output projection -> d_out fp32
    run_gemm(gahi, galo, 4096, 0, 0, wohi, wolo, 4096, 0, 0,
             4096, 2048, 4096, 1, 0, out, 0, 0, 2048, 0, 0,
             0, 0, 0, 0, 1.0f, 0, 0);
}

// round 4
// speedup vs baseline: 1.5068x; 1.0765x over previous
#include <cuda_runtime.h>
#include <cuda_bf16.h>
#include <cstdint>

typedef __nv_bfloat16 bf16;

// B=2, T=2048, E=2048, V=4096, NH=8, KD=256, HD=512
#define SZ_TE ((size_t)4096*2048)
#define SZ_TV ((size_t)4096*4096)
#define SZ_E2 ((size_t)2048*2048)
#define SZ_VE ((size_t)4096*2048)
#define SZ_EV ((size_t)2048*4096)
#define SZ_S  ((size_t)16*2048*2048)

// ---- scratch ----
__device__ bf16  g_xhi[SZ_TE],  g_xlo[SZ_TE];
__device__ bf16  g_wqhi[SZ_E2], g_wqlo[SZ_E2];
__device__ bf16  g_wkhi[SZ_E2], g_wklo[SZ_E2];
__device__ bf16  g_wvhi[SZ_VE], g_wvlo[SZ_VE];
__device__ bf16  g_wghi[SZ_VE], g_wglo[SZ_VE];
__device__ bf16  g_wohi[SZ_EV], g_wolo[SZ_EV];
__device__ bf16  g_qrhi[SZ_TE], g_qrlo[SZ_TE];
__device__ bf16  g_krhi[SZ_TE], g_krlo[SZ_TE];
__device__ bf16  g_vthi[SZ_TV], g_vtlo[SZ_TV];   // v transposed: per b, (V rows, T cols)
__device__ float g_gf[SZ_TV];
__device__ bf16  g_shi[SZ_S],   g_slo[SZ_S];
__device__ float g_invd[16*2048];
__device__ float g_of[SZ_TV];
__device__ bf16  g_gahi[SZ_TV], g_galo[SZ_TV];

// ---- helpers ----
__device__ __forceinline__ void split_store(bf16* hi, bf16* lo, long idx, float v) {
    bf16 h = __float2bfloat16(v);
    hi[idx] = h;
    lo[idx] = __float2bfloat16(v - __bfloat162float(h));
}
__device__ __forceinline__ void split2(bf16* hi, bf16* lo, long idx, float a, float b) {
    bf16 ah = __float2bfloat16(a), bh = __float2bfloat16(b);
    __nv_bfloat162 hh; hh.x = ah; hh.y = bh;
    *(__nv_bfloat162*)(hi + idx) = hh;
    __nv_bfloat162 ll;
    ll.x = __float2bfloat16(a - __bfloat162float(ah));
    ll.y = __float2bfloat16(b - __bfloat162float(bh));
    *(__nv_bfloat162*)(lo + idx) = ll;
}
__device__ __forceinline__ void cp16(uint32_t dst, const void* src) {
    asm volatile("cp.async.cg.shared.global [%0], [%1], 16;\n" :: "r"(dst), "l"(src));
}

#define LDSM4(R, addr) asm volatile( \
    "ldmatrix.sync.aligned.m8n8.x4.shared.b16 {%0,%1,%2,%3}, [%4];\n" \
    : "=r"((R)[0]), "=r"((R)[1]), "=r"((R)[2]), "=r"((R)[3]) : "r"(addr))

#define MMA(d, a, b) asm volatile( \
    "mma.sync.aligned.m16n8k16.row.col.f32.bf16.bf16.f32 " \
    "{%0,%1,%2,%3}, {%4,%5,%6,%7}, {%8,%9}, {%0,%1,%2,%3};\n" \
    : "+f"((d)[0]), "+f"((d)[1]), "+f"((d)[2]), "+f"((d)[3]) \
    : "r"((a)[0]), "r"((a)[1]), "r"((a)[2]), "r"((a)[3]), "r"((b)[0]), "r"((b)[1]))

// ---- generic bf16x3 GEMM: C[M,N] = A[M,K] * B^T, B is (N,K) row-major ----
// CTA tile 128(M) x 256(N), K-step 32, 3-stage cp.async pipeline.
// epi: 0 = fp32 store, 1 = split store, 2 = *decay_mask then split store,
//      3 = *inv[row] then fp32 store, 4 = rotary(+scale) then split store
struct GP {
    const bf16 *Ahi, *Alo, *Bhi, *Blo;
    float* Cf; bf16 *Chi, *Clo;
    const float* dm; const float* inv; const float* sinp; const float* cosp;
    long aSb, aSh, bSb, bSh, cSb, cSh;   // off = bb*Sb + hh*Sh (bb=z>>3, hh=z&7)
    int lda, ldb, ldc;
    int M, N, K;
    int epi, causalSkip, causalK;
    float scale;
};

// per-stage smem elems: Ahi 128*40 + Alo 128*40 + Bhi 256*40 + Blo 256*40
#define ST_ELEMS 30720
#define OFF_ALO  5120
#define OFF_BHI  10240
#define OFF_BLO  20480
#define SMEM_BYTES (3 * ST_ELEMS * 2)

__global__ void __launch_bounds__(256, 1) gemm_bf16x3(const __grid_constant__ GP p) {
    extern __shared__ __align__(16) bf16 smem[];
    const int z    = blockIdx.z;
    const int bb   = z >> 3, hh = z & 7;
    const int row0 = blockIdx.y * 128;
    const int col0 = blockIdx.x * 256;
    if (p.causalSkip && col0 > row0) return;   // strictly-upper tile

    const bf16* __restrict__ Ahi = p.Ahi + (long)bb * p.aSb + (long)hh * p.aSh;
    const bf16* __restrict__ Alo = p.Alo + (long)bb * p.aSb + (long)hh * p.aSh;
    const bf16* __restrict__ Bhi = p.Bhi + (long)bb * p.bSb + (long)hh * p.bSh;
    const bf16* __restrict__ Blo = p.Blo + (long)bb * p.bSb + (long)hh * p.bSh;

    const int tid  = threadIdx.x;
    const int lane = tid & 31;
    const int wid  = tid >> 5;
    const int wm   = (wid >> 2) * 64;     // 2x4 warp grid, 64x64 warp tile
    const int wn   = (wid & 3) * 64;
    const uint32_t sbase = (uint32_t)__cvta_generic_to_shared(smem);

    const int Keff = p.causalK ? min(p.K, row0 + 128) : p.K;
    const int nk   = Keff >> 5;

    float acc[4][8][4];
    #pragma unroll
    for (int i = 0; i < 4; i++)
        #pragma unroll
        for (int j = 0; j < 8; j++)
            #pragma unroll
            for (int e = 0; e < 4; e++) acc[i][j][e] = 0.f;

    auto issue = [&](int it) {
        if (it < nk) {
            const int k0 = it << 5;
            const int st = (it % 3) * ST_ELEMS;
            // A: 1024 16B-chunks (2 comps x 128 rows x 4)
            #pragma unroll
            for (int i = 0; i < 4; i++) {
                const int idx  = tid + (i << 8);
                const int comp = idx >> 9, ch = idx & 511;
                const int row  = ch >> 2, cc = (ch & 3) << 3;
                const long off = (long)(row0 + row) * p.lda + k0 + cc;
                const uint32_t d = sbase + (uint32_t)(st + comp * OFF_ALO + row * 40 + cc) * 2;
                cp16(d, (comp ? Alo : Ahi) + off);
            }
            // B: 2048 16B-chunks (2 comps x 256 rows x 4)
            #pragma unroll
            for (int i = 0; i < 8; i++) {
                const int idx  = tid + (i << 8);
                const int comp = idx >> 10, ch = idx & 1023;
                const int row  = ch >> 2, cc = (ch & 3) << 3;
                const long off = (long)(col0 + row) * p.ldb + k0 + cc;
                const uint32_t d = sbase +
                    (uint32_t)(st + OFF_BHI + comp * 10240 + row * 40 + cc) * 2;
                cp16(d, (comp ? Blo : Bhi) + off);
            }
        }
        asm volatile("cp.async.commit_group;\n");
    };

    issue(0); issue(1); issue(2);

    for (int it = 0; it < nk; it++) {
        asm volatile("cp.async.wait_group 2;\n");
        __syncthreads();
        const int st = (it % 3) * ST_ELEMS;

        #pragma unroll
        for (int kk = 0; kk < 32; kk += 16) {
            uint32_t ah[4][4], al[4][4], bh[4][4], bl[4][4];
            const int mat = lane >> 3, t7 = lane & 7;
            const int arow = ((mat & 1) << 3) + t7;
            const int acol = (mat >> 1) << 3;
            #pragma unroll
            for (int fm = 0; fm < 4; fm++) {
                const uint32_t ad = sbase +
                    (uint32_t)(st + (wm + fm * 16 + arow) * 40 + kk + acol) * 2;
                LDSM4(ah[fm], ad);
                LDSM4(al[fm], ad + OFF_ALO * 2);
            }
            const int brow = ((mat >> 1) << 3) + t7;
            const int bcol = (mat & 1) << 3;
            #pragma unroll
            for (int fp = 0; fp < 4; fp++) {
                const uint32_t bd = sbase +
                    (uint32_t)(st + OFF_BHI + (wn + fp * 16 + brow) * 40 + kk + bcol) * 2;
                LDSM4(bh[fp], bd);
                LDSM4(bl[fp], bd + 10240 * 2);
            }
            #pragma unroll
            for (int fm = 0; fm < 4; fm++)
                #pragma unroll
                for (int fn = 0; fn < 8; fn++) {
                    uint32_t* bhp = &bh[fn >> 1][(fn & 1) * 2];
                    uint32_t* blp = &bl[fn >> 1][(fn & 1) * 2];
                    MMA(acc[fm][fn], ah[fm], bhp);
                    MMA(acc[fm][fn], ah[fm], blp);
                    MMA(acc[fm][fn], al[fm], bhp);
                }
        }
        __syncthreads();
        issue(it + 3);
    }

    // epilogue (pair-based: x0 at even col c, x1 at c+1)
    const long cb = (long)bb * p.cSb + (long)hh * p.cSh;
    const float* dmh = p.dm ? (p.dm + (long)hh * (long)p.M * p.N) : (const float*)0;
    #pragma unroll
    for (int fm = 0; fm < 4; fm++)
        #pragma unroll
        for (int fn = 0; fn < 8; fn++)
            #pragma unroll
            for (int half = 0; half < 2; half++) {
                const int r = row0 + wm + fm * 16 + (lane >> 2) + half * 8;
                const int c = col0 + wn + fn * 8 + ((lane & 3) << 1);
                float x0 = acc[fm][fn][half * 2];
                float x1 = acc[fm][fn][half * 2 + 1];
                const long ci = cb + (long)r * p.ldc + c;
                if (p.epi == 0) {
                    p.Cf[ci] = x0; p.Cf[ci + 1] = x1;
                } else if (p.epi == 1) {
                    split2(p.Chi, p.Clo, ci, x0, x1);
                } else if (p.epi == 2) {
                    x0 *= dmh[(long)r * p.N + c];
                    x1 *= dmh[(long)r * p.N + c + 1];
                    split2(p.Chi, p.Clo, ci, x0, x1);
                } else if (p.epi == 3) {
                    const float iv = p.inv[(long)z * p.M + r];
                    p.Cf[ci] = x0 * iv; p.Cf[ci + 1] = x1 * iv;
                } else {   // rotary (+ optional scale), split store
                    const int t = r & 2047, dd = c & 255;
                    const float c0 = p.cosp[t * 256 + dd],     s0 = p.sinp[t * 256 + dd];
                    const float c1 = p.cosp[t * 256 + dd + 1], s1 = p.sinp[t * 256 + dd + 1];
                    const float y0 = (x0 * c0 - x1 * s0) * p.scale;
                    const float y1 = (x1 * c1 + x0 * s1) * p.scale;
                    split2(p.Chi, p.Clo, ci, y0, y1);
                }
            }
}

// ---- merged split kernel: all 6 fp32->bf16hi/lo conversions in ONE launch ----
struct SplitSeg { const float* src; bf16* hi; bf16* lo; long n4; };
struct SplitArgs { SplitSeg seg[6]; };

__global__ void split_all_kernel(const __grid_constant__ SplitArgs a) {
    const SplitSeg s = a.seg[blockIdx.y];
    long i = (long)blockIdx.x * blockDim.x + threadIdx.x;
    const long stride = (long)gridDim.x * blockDim.x;
    for (; i < s.n4; i += stride) {
        const float4 v = *(const float4*)(s.src + i * 4);
        bf16 h0 = __float2bfloat16(v.x), h1 = __float2bfloat16(v.y);
        bf16 h2 = __float2bfloat16(v.z), h3 = __float2bfloat16(v.w);
        __nv_bfloat162 hh0; hh0.x = h0; hh0.y = h1;
        __nv_bfloat162 hh1; hh1.x = h2; hh1.y = h3;
        uint2 hv; hv.x = *(uint32_t*)&hh0; hv.y = *(uint32_t*)&hh1;
        *(uint2*)(s.hi + i * 4) = hv;
        __nv_bfloat162 ll0, ll1;
        ll0.x = __float2bfloat16(v.x - __bfloat162float(h0));
        ll0.y = __float2bfloat16(v.y - __bfloat162float(h1));
        ll1.x = __float2bfloat16(v.z - __bfloat162float(h2));
        ll1.y = __float2bfloat16(v.w - __bfloat162float(h3));
        uint2 lv; lv.x = *(uint32_t*)&ll0; lv.y = *(uint32_t*)&ll1;
        *(uint2*)(s.lo + i * 4) = lv;
    }
}

__global__ void rowsum_kernel(const bf16* __restrict__ Shi, const bf16* __restrict__ Slo,
                              float* __restrict__ inv) {
    const int t = blockIdx.x, z = blockIdx.y;
    const long rb = ((long)z * 2048 + t) * 2048;
    float s = 0.f;
    for (int i = threadIdx.x; i <= t; i += 256)
        s += __bfloat162float(Shi[rb + i]) + __bfloat162float(Slo[rb + i]);
    #pragma unroll
    for (int o = 16; o; o >>= 1) s += __shfl_down_sync(0xffffffffu, s, o);
    __shared__ float red[8];
    if ((threadIdx.x & 31) == 0) red[threadIdx.x >> 5] = s;
    __syncthreads();
    if (threadIdx.x < 8) {
        float v = red[threadIdx.x];
        #pragma unroll
        for (int o = 4; o; o >>= 1) v += __shfl_down_sync(0xffu, v, o);
        if (threadIdx.x == 0) inv[(long)z * 2048 + t] = 1.0f / fmaxf(fabsf(v), 1.0f);
    }
}

__global__ void gate_kernel(const float* __restrict__ o, const float* __restrict__ g,
                            bf16* __restrict__ ghi, bf16* __restrict__ glo) {
    const int blk = blockIdx.x;           // bt*8 + h
    const int h   = blk & 7;
    const long bt = blk >> 3;
    const long base = bt * 4096 + h * 512;
    const int tid = threadIdx.x;          // 128 threads, 4 elems each
    float4 x = *(const float4*)(o + base + tid * 4);
    float ss = x.x * x.x + x.y * x.y + x.z * x.z + x.w * x.w;
    #pragma unroll
    for (int off = 16; off; off >>= 1) ss += __shfl_down_sync(0xffffffffu, ss, off);
    __shared__ float ws[4];
    __shared__ float tot;
    if ((tid & 31) == 0) ws[tid >> 5] = ss;
    __syncthreads();
    if (tid == 0) tot = ws[0] + ws[1] + ws[2] + ws[3];
    __syncthreads();
    const float r = rsqrtf(tot * (1.0f / 512.0f) + 1e-6f);
    float4 gv = *(const float4*)(g + base + tid * 4);
    const float xv[4] = {x.x, x.y, x.z, x.w};
    const float gg[4] = {gv.x, gv.y, gv.z, gv.w};
    #pragma unroll
    for (int j = 0; j < 4; j++) {
        const float sig = 1.0f / (1.0f + expf(-gg[j]));
        const float val = gg[j] * sig * xv[j] * r;
        split_store(ghi, glo, base + tid * 4 + j, val);
    }
}

// ---- host side ----
static void run_gemm(const bf16* Ahi, const bf16* Alo, int lda, long aSb, long aSh,
                     const bf16* Bhi, const bf16* Blo, int ldb, long bSb, long bSh,
                     int M, int N, int K, int batches, int epi,
                     float* Cf, bf16* Chi, bf16* Clo, int ldc, long cSb, long cSh,
                     const float* dm, const float* inv,
                     const float* sinp, const float* cosp, float scale,
                     int causalSkip, int causalK) {
    GP p;
    p.Ahi = Ahi; p.Alo = Alo; p.Bhi = Bhi; p.Blo = Blo;
    p.Cf = Cf; p.Chi = Chi; p.Clo = Clo;
    p.dm = dm; p.inv = inv; p.sinp = sinp; p.cosp = cosp;
    p.aSb = aSb; p.aSh = aSh; p.bSb = bSb; p.bSh = bSh; p.cSb = cSb; p.cSh = cSh;
    p.lda = lda; p.ldb = ldb; p.ldc = ldc;
    p.M = M; p.N = N; p.K = K;
    p.epi = epi; p.causalSkip = causalSkip; p.causalK = causalK; p.scale = scale;
    dim3 grid(N / 256, M / 128, batches);
    gemm_bf16x3<<<grid, 256, SMEM_BYTES>>>(p);
}

#define GETP(ptr, sym, T) T* ptr; { void* _p = 0; cudaGetSymbolAddress(&_p, sym); ptr = (T*)_p; }

extern "C" void kernel_launch(void* const* d_in, const int* in_sizes, int n_in,
                              void* d_out, int out_size) {
    const float* hs   = (const float*)d_in[0];
    const float* sinp = (const float*)d_in[1];
    const float* cosp = (const float*)d_in[2];
    const float* dm   = (const float*)d_in[3];
    const float* wq   = (const float*)d_in[4];
    const float* wk   = (const float*)d_in[5];
    const float* wv   = (const float*)d_in[6];
    const float* wg   = (const float*)d_in[7];
    const float* wo   = (const float*)d_in[8];
    float* out = (float*)d_out;

    cudaFuncSetAttribute(gemm_bf16x3, cudaFuncAttributeMaxDynamicSharedMemorySize, SMEM_BYTES);

    GETP(xhi,  g_xhi,  bf16)  GETP(xlo,  g_xlo,  bf16)
    GETP(wqhi, g_wqhi, bf16)  GETP(wqlo, g_wqlo, bf16)
    GETP(wkhi, g_wkhi, bf16)  GETP(wklo, g_wklo, bf16)
    GETP(wvhi, g_wvhi, bf16)  GETP(wvlo, g_wvlo, bf16)
    GETP(wghi, g_wghi, bf16)  GETP(wglo, g_wglo, bf16)
    GETP(wohi, g_wohi, bf16)  GETP(wolo, g_wolo, bf16)
    GETP(qrhi, g_qrhi, bf16)  GETP(qrlo, g_qrlo, bf16)
    GETP(krhi, g_krhi, bf16)  GETP(krlo, g_krlo, bf16)
    GETP(vthi, g_vthi, bf16)  GETP(vtlo, g_vtlo, bf16)
    GETP(gf,   g_gf,   float)
    GETP(shi,  g_shi,  bf16)  GETP(slo,  g_slo,  bf16)
    GETP(invp, g_invd, float)
    GETP(of,   g_of,   float)
    GETP(gahi, g_gahi, bf16)  GETP(galo, g_galo, bf16)

    // 1) ONE launch: split all fp32 inputs into bf16 hi/lo
    SplitArgs sa;
    sa.seg[0] = { hs, xhi,  xlo,  ((long)4096 * 2048) / 4 };
    sa.seg[1] = { wq, wqhi, wqlo, ((long)2048 * 2048) / 4 };
    sa.seg[2] = { wk, wkhi, wklo, ((long)2048 * 2048) / 4 };
    sa.seg[3] = { wv, wvhi, wvlo, ((long)4096 * 2048) / 4 };
    sa.seg[4] = { wg, wghi, wglo, ((long)4096 * 2048) / 4 };
    sa.seg[5] = { wo, wohi, wolo, ((long)2048 * 4096) / 4 };
    split_all_kernel<<<dim3(512, 6), 256>>>(sa);

    // 2) q/k projections with fused rotary (k scaled by 1/16) -> split qr/kr
    run_gemm(xhi, xlo, 2048, 0, 0, wqhi, wqlo, 2048, 0, 0,
             4096, 2048, 2048, 1, 4, 0, qrhi, qrlo, 2048, 0, 0,
             0, 0, sinp, cosp, 1.0f, 0, 0);
    run_gemm(xhi, xlo, 2048, 0, 0, wkhi, wklo, 2048, 0, 0,
             4096, 2048, 2048, 1, 4, 0, krhi, krlo, 2048, 0, 0,
             0, 0, sinp, cosp, 0.0625f, 0, 0);

    // 3) vT = Wv @ x^T per batch: (V, T)
    run_gemm(wvhi, wvlo, 2048, 0, 0, xhi, xlo, 2048, 0, (long)2048 * 2048,
             4096, 2048, 2048, 2, 1, 0, vthi, vtlo, 2048, 0, (long)4096 * 2048,
             0, 0, 0, 0, 1.0f, 0, 0);

    // 4) g projection -> fp32
    run_gemm(xhi, xlo, 2048, 0, 0, wghi, wglo, 2048, 0, 0,
             4096, 4096, 2048, 1, 0, gf, 0, 0, 4096, 0, 0,
             0, 0, 0, 0, 1.0f, 0, 0);

    // 5) S = (qr . kr^T) * dm, batched over 16 (b,h); skip strictly-upper tiles
    run_gemm(qrhi, qrlo, 2048, (long)2048 * 2048, 256,
             krhi, krlo, 2048, (long)2048 * 2048, 256,
             2048, 2048, 256, 16, 2, 0, shi, slo, 2048,
             (long)8 * 2048 * 2048, (long)2048 * 2048,
             dm, 0, 0, 0, 1.0f, 1, 0);

    // 6) inv = 1/max(|rowsum|,1)
    rowsum_kernel<<<dim3(2048, 16), 256>>>(shi, slo, invp);

    // 7) O = inv * (S @ vT^T), K causally limited; written as (b,t,h*HD+d)
    run_gemm(shi, slo, 2048, (long)8 * 2048 * 2048, (long)2048 * 2048,
             vthi, vtlo, 2048, (long)4096 * 2048, (long)512 * 2048,
             2048, 512, 2048, 16, 3, of, 0, 0, 4096,
             (long)2048 * 4096, 512,
             0, invp, 0, 0, 1.0f, 0, 1);

    // 8) per-head RMS norm + silu(g) gating -> split gated
    gate_kernel<<<32768, 128>>>(of, gf, gahi, galo);

    // 9) output projection -> d_out fp32
    run_gemm(gahi, galo, 4096, 0, 0, wohi, wolo, 4096, 0, 0,
             4096, 2048, 4096, 1, 0, out, 0, 0, 2048, 0, 0,
             0, 0, 0, 0, 1.0f, 0, 0);
}

// round 5
// speedup vs baseline: 1.8011x; 1.1953x over previous
#include <cuda_runtime.h>
#include <cuda_bf16.h>
#include <cstdint>

typedef __nv_bfloat16 bf16;

// B=2, T=2048, E=2048, V=4096, NH=8, KD=256, HD=512
#define SZ_TE ((size_t)4096*2048)
#define SZ_TV ((size_t)4096*4096)
#define SZ_E2 ((size_t)2048*2048)
#define SZ_VE ((size_t)4096*2048)
#define SZ_EV ((size_t)2048*4096)
#define SZ_S  ((size_t)16*2048*2048)

// ---- scratch ----
__device__ bf16  g_xhi[SZ_TE],  g_xlo[SZ_TE];
__device__ bf16  g_wqhi[SZ_E2], g_wqlo[SZ_E2];
__device__ bf16  g_wkhi[SZ_E2], g_wklo[SZ_E2];
__device__ bf16  g_wvhi[SZ_VE], g_wvlo[SZ_VE];
__device__ bf16  g_wghi[SZ_VE], g_wglo[SZ_VE];
__device__ bf16  g_wohi[SZ_EV], g_wolo[SZ_EV];
__device__ bf16  g_qrhi[SZ_TE], g_qrlo[SZ_TE];
__device__ bf16  g_krhi[SZ_TE], g_krlo[SZ_TE];
__device__ bf16  g_vthi[SZ_TV], g_vtlo[SZ_TV];   // v transposed: per b, (V rows, T cols)
__device__ float g_gf[SZ_TV];
__device__ bf16  g_shi[SZ_S],   g_slo[SZ_S];
__device__ float g_invd[16*2048];
__device__ float g_of[SZ_TV];
__device__ bf16  g_gahi[SZ_TV], g_galo[SZ_TV];

// ---- helpers ----
__device__ __forceinline__ void split_store(bf16* hi, bf16* lo, long idx, float v) {
    bf16 h = __float2bfloat16(v);
    hi[idx] = h;
    lo[idx] = __float2bfloat16(v - __bfloat162float(h));
}
__device__ __forceinline__ void split2(bf16* hi, bf16* lo, long idx, float a, float b) {
    bf16 ah = __float2bfloat16(a), bh = __float2bfloat16(b);
    __nv_bfloat162 hh; hh.x = ah; hh.y = bh;
    *(__nv_bfloat162*)(hi + idx) = hh;
    __nv_bfloat162 ll;
    ll.x = __float2bfloat16(a - __bfloat162float(ah));
    ll.y = __float2bfloat16(b - __bfloat162float(bh));
    *(__nv_bfloat162*)(lo + idx) = ll;
}
__device__ __forceinline__ void cp16(uint32_t dst, const void* src) {
    asm volatile("cp.async.cg.shared.global [%0], [%1], 16;\n" :: "r"(dst), "l"(src));
}

#define LDSM4(R, addr) asm volatile( \
    "ldmatrix.sync.aligned.m8n8.x4.shared.b16 {%0,%1,%2,%3}, [%4];\n" \
    : "=r"((R)[0]), "=r"((R)[1]), "=r"((R)[2]), "=r"((R)[3]) : "r"(addr))

#define MMA(d, a, b) asm volatile( \
    "mma.sync.aligned.m16n8k16.row.col.f32.bf16.bf16.f32 " \
    "{%0,%1,%2,%3}, {%4,%5,%6,%7}, {%8,%9}, {%0,%1,%2,%3};\n" \
    : "+f"((d)[0]), "+f"((d)[1]), "+f"((d)[2]), "+f"((d)[3]) \
    : "r"((a)[0]), "r"((a)[1]), "r"((a)[2]), "r"((a)[3]), "r"((b)[0]), "r"((b)[1]))

// ---- generic bf16x3 GEMM: C[M,N] = A[M,K] * B^T, B is (N,K) row-major ----
// CTA tile 128(M) x 128(N), 128 threads (4 warps, 64x64 warp tiles),
// K-step 32, 2-stage cp.async pipeline, 2 CTAs/SM for cross-CTA overlap.
// epi: 0 = fp32 store, 1 = split store, 2 = *decay_mask then split store,
//      3 = *inv[row] then fp32 store, 4 = rotary(+scale) then split store
struct GP {
    const bf16 *Ahi, *Alo, *Bhi, *Blo;
    float* Cf; bf16 *Chi, *Clo;
    const float* dm; const float* inv; const float* sinp; const float* cosp;
    long aSb, aSh, bSb, bSh, cSb, cSh;   // off = bb*Sb + hh*Sh (bb=z>>3, hh=z&7)
    int lda, ldb, ldc;
    int M, N, K;
    int epi, causalSkip, causalK;
    float scale;
};

// per-stage smem elems: Ahi 128*40 + Alo 128*40 + Bhi 128*40 + Blo 128*40
#define ST_ELEMS 20480
#define OFF_ALO  5120
#define OFF_BHI  10240
#define SMEM_BYTES (2 * ST_ELEMS * 2)   // 81920 B -> 2 CTAs/SM

__global__ void __launch_bounds__(128, 2) gemm_bf16x3(const __grid_constant__ GP p) {
    extern __shared__ __align__(16) bf16 smem[];
    const int z    = blockIdx.z;
    const int bb   = z >> 3, hh = z & 7;
    const int row0 = blockIdx.y * 128;
    const int col0 = blockIdx.x * 128;
    if (p.causalSkip && col0 > row0) return;   // strictly-upper tile

    const bf16* __restrict__ Ahi = p.Ahi + (long)bb * p.aSb + (long)hh * p.aSh;
    const bf16* __restrict__ Alo = p.Alo + (long)bb * p.aSb + (long)hh * p.aSh;
    const bf16* __restrict__ Bhi = p.Bhi + (long)bb * p.bSb + (long)hh * p.bSh;
    const bf16* __restrict__ Blo = p.Blo + (long)bb * p.bSb + (long)hh * p.bSh;

    const int tid  = threadIdx.x;
    const int lane = tid & 31;
    const int wid  = tid >> 5;
    const int wm   = (wid >> 1) * 64;     // 2x2 warp grid, 64x64 warp tile
    const int wn   = (wid & 1) * 64;
    const uint32_t sbase = (uint32_t)__cvta_generic_to_shared(smem);

    const int Keff = p.causalK ? min(p.K, row0 + 128) : p.K;
    const int nk   = Keff >> 5;

    float acc[4][8][4];
    #pragma unroll
    for (int i = 0; i < 4; i++)
        #pragma unroll
        for (int j = 0; j < 8; j++)
            #pragma unroll
            for (int e = 0; e < 4; e++) acc[i][j][e] = 0.f;

    auto issue = [&](int it) {
        if (it < nk) {
            const int k0 = it << 5;
            const int st = (it & 1) * ST_ELEMS;
            // A + B: each 1024 16B-chunks (2 comps x 128 rows x 4)
            #pragma unroll
            for (int i = 0; i < 8; i++) {
                const int idx  = tid + (i << 7);
                const int comp = idx >> 9, ch = idx & 511;
                const int row  = ch >> 2, cc = (ch & 3) << 3;
                const long aoff = (long)(row0 + row) * p.lda + k0 + cc;
                const long boff = (long)(col0 + row) * p.ldb + k0 + cc;
                const uint32_t d = sbase + (uint32_t)(st + comp * OFF_ALO + row * 40 + cc) * 2;
                cp16(d, (comp ? Alo : Ahi) + aoff);
                cp16(d + OFF_BHI * 2, (comp ? Blo : Bhi) + boff);
            }
        }
        asm volatile("cp.async.commit_group;\n");
    };

    issue(0); issue(1);

    for (int it = 0; it < nk; it++) {
        asm volatile("cp.async.wait_group 1;\n");
        __syncthreads();
        const int st = (it & 1) * ST_ELEMS;

        #pragma unroll
        for (int kk = 0; kk < 32; kk += 16) {
            uint32_t ah[4][4], al[4][4], bh[4][4], bl[4][4];
            const int mat = lane >> 3, t7 = lane & 7;
            const int arow = ((mat & 1) << 3) + t7;
            const int acol = (mat >> 1) << 3;
            #pragma unroll
            for (int fm = 0; fm < 4; fm++) {
                const uint32_t ad = sbase +
                    (uint32_t)(st + (wm + fm * 16 + arow) * 40 + kk + acol) * 2;
                LDSM4(ah[fm], ad);
                LDSM4(al[fm], ad + OFF_ALO * 2);
            }
            const int brow = ((mat >> 1) << 3) + t7;
            const int bcol = (mat & 1) << 3;
            #pragma unroll
            for (int fp = 0; fp < 4; fp++) {
                const uint32_t bd = sbase +
                    (uint32_t)(st + OFF_BHI + (wn + fp * 16 + brow) * 40 + kk + bcol) * 2;
                LDSM4(bh[fp], bd);
                LDSM4(bl[fp], bd + OFF_ALO * 2);
            }
            #pragma unroll
            for (int fm = 0; fm < 4; fm++)
                #pragma unroll
                for (int fn = 0; fn < 8; fn++) {
                    uint32_t* bhp = &bh[fn >> 1][(fn & 1) * 2];
                    uint32_t* blp = &bl[fn >> 1][(fn & 1) * 2];
                    MMA(acc[fm][fn], ah[fm], bhp);
                    MMA(acc[fm][fn], ah[fm], blp);
                    MMA(acc[fm][fn], al[fm], bhp);
                }
        }
        __syncthreads();
        issue(it + 2);
    }

    // epilogue (pair-based: x0 at even col c, x1 at c+1)
    const long cb = (long)bb * p.cSb + (long)hh * p.cSh;
    const float* dmh = p.dm ? (p.dm + (long)hh * (long)p.M * p.N) : (const float*)0;
    #pragma unroll
    for (int fm = 0; fm < 4; fm++)
        #pragma unroll
        for (int fn = 0; fn < 8; fn++)
            #pragma unroll
            for (int half = 0; half < 2; half++) {
                const int r = row0 + wm + fm * 16 + (lane >> 2) + half * 8;
                const int c = col0 + wn + fn * 8 + ((lane & 3) << 1);
                float x0 = acc[fm][fn][half * 2];
                float x1 = acc[fm][fn][half * 2 + 1];
                const long ci = cb + (long)r * p.ldc + c;
                if (p.epi == 0) {
                    p.Cf[ci] = x0; p.Cf[ci + 1] = x1;
                } else if (p.epi == 1) {
                    split2(p.Chi, p.Clo, ci, x0, x1);
                } else if (p.epi == 2) {
                    x0 *= dmh[(long)r * p.N + c];
                    x1 *= dmh[(long)r * p.N + c + 1];
                    split2(p.Chi, p.Clo, ci, x0, x1);
                } else if (p.epi == 3) {
                    const float iv = p.inv[(long)z * p.M + r];
                    p.Cf[ci] = x0 * iv; p.Cf[ci + 1] = x1 * iv;
                } else {   // rotary (+ optional scale), split store
                    const int t = r & 2047, dd = c & 255;
                    const float c0 = p.cosp[t * 256 + dd],     s0 = p.sinp[t * 256 + dd];
                    const float c1 = p.cosp[t * 256 + dd + 1], s1 = p.sinp[t * 256 + dd + 1];
                    const float y0 = (x0 * c0 - x1 * s0) * p.scale;
                    const float y1 = (x1 * c1 + x0 * s1) * p.scale;
                    split2(p.Chi, p.Clo, ci, y0, y1);
                }
            }
}

// ---- merged split kernel: all 6 fp32->bf16hi/lo conversions in ONE launch ----
struct SplitSeg { const float* src; bf16* hi; bf16* lo; long n4; };
struct SplitArgs { SplitSeg seg[6]; };

__global__ void split_all_kernel(const __grid_constant__ SplitArgs a) {
    const SplitSeg s = a.seg[blockIdx.y];
    long i = (long)blockIdx.x * blockDim.x + threadIdx.x;
    const long stride = (long)gridDim.x * blockDim.x;
    for (; i < s.n4; i += stride) {
        const float4 v = *(const float4*)(s.src + i * 4);
        bf16 h0 = __float2bfloat16(v.x), h1 = __float2bfloat16(v.y);
        bf16 h2 = __float2bfloat16(v.z), h3 = __float2bfloat16(v.w);
        __nv_bfloat162 hh0; hh0.x = h0; hh0.y = h1;
        __nv_bfloat162 hh1; hh1.x = h2; hh1.y = h3;
        uint2 hv; hv.x = *(uint32_t*)&hh0; hv.y = *(uint32_t*)&hh1;
        *(uint2*)(s.hi + i * 4) = hv;
        __nv_bfloat162 ll0, ll1;
        ll0.x = __float2bfloat16(v.x - __bfloat162float(h0));
        ll0.y = __float2bfloat16(v.y - __bfloat162float(h1));
        ll1.x = __float2bfloat16(v.z - __bfloat162float(h2));
        ll1.y = __float2bfloat16(v.w - __bfloat162float(h3));
        uint2 lv; lv.x = *(uint32_t*)&ll0; lv.y = *(uint32_t*)&ll1;
        *(uint2*)(s.lo + i * 4) = lv;
    }
}

__global__ void rowsum_kernel(const bf16* __restrict__ Shi, const bf16* __restrict__ Slo,
                              float* __restrict__ inv) {
    const int t = blockIdx.x, z = blockIdx.y;
    const long rb = ((long)z * 2048 + t) * 2048;
    float s = 0.f;
    for (int i = threadIdx.x; i <= t; i += 256)
        s += __bfloat162float(Shi[rb + i]) + __bfloat162float(Slo[rb + i]);
    #pragma unroll
    for (int o = 16; o; o >>= 1) s += __shfl_down_sync(0xffffffffu, s, o);
    __shared__ float red[8];
    if ((threadIdx.x & 31) == 0) red[threadIdx.x >> 5] = s;
    __syncthreads();
    if (threadIdx.x < 8) {
        float v = red[threadIdx.x];
        #pragma unroll
        for (int o = 4; o; o >>= 1) v += __shfl_down_sync(0xffu, v, o);
        if (threadIdx.x == 0) inv[(long)z * 2048 + t] = 1.0f / fmaxf(fabsf(v), 1.0f);
    }
}

__global__ void gate_kernel(const float* __restrict__ o, const float* __restrict__ g,
                            bf16* __restrict__ ghi, bf16* __restrict__ glo) {
    const int blk = blockIdx.x;           // bt*8 + h
    const int h   = blk & 7;
    const long bt = blk >> 3;
    const long base = bt * 4096 + h * 512;
    const int tid = threadIdx.x;          // 128 threads, 4 elems each
    float4 x = *(const float4*)(o + base + tid * 4);
    float ss = x.x * x.x + x.y * x.y + x.z * x.z + x.w * x.w;
    #pragma unroll
    for (int off = 16; off; off >>= 1) ss += __shfl_down_sync(0xffffffffu, ss, off);
    __shared__ float ws[4];
    __shared__ float tot;
    if ((tid & 31) == 0) ws[tid >> 5] = ss;
    __syncthreads();
    if (tid == 0) tot = ws[0] + ws[1] + ws[2] + ws[3];
    __syncthreads();
    const float r = rsqrtf(tot * (1.0f / 512.0f) + 1e-6f);
    float4 gv = *(const float4*)(g + base + tid * 4);
    const float xv[4] = {x.x, x.y, x.z, x.w};
    const float gg[4] = {gv.x, gv.y, gv.z, gv.w};
    #pragma unroll
    for (int j = 0; j < 4; j++) {
        const float sig = 1.0f / (1.0f + expf(-gg[j]));
        const float val = gg[j] * sig * xv[j] * r;
        split_store(ghi, glo, base + tid * 4 + j, val);
    }
}

// ---- host side ----
static void run_gemm(const bf16* Ahi, const bf16* Alo, int lda, long aSb, long aSh,
                     const bf16* Bhi, const bf16* Blo, int ldb, long bSb, long bSh,
                     int M, int N, int K, int batches, int epi,
                     float* Cf, bf16* Chi, bf16* Clo, int ldc, long cSb, long cSh,
                     const float* dm, const float* inv,
                     const float* sinp, const float* cosp, float scale,
                     int causalSkip, int causalK) {
    GP p;
    p.Ahi = Ahi; p.Alo = Alo; p.Bhi = Bhi; p.Blo = Blo;
    p.Cf = Cf; p.Chi = Chi; p.Clo = Clo;
    p.dm = dm; p.inv = inv; p.sinp = sinp; p.cosp = cosp;
    p.aSb = aSb; p.aSh = aSh; p.bSb = bSb; p.bSh = bSh; p.cSb = cSb; p.cSh = cSh;
    p.lda = lda; p.ldb = ldb; p.ldc = ldc;
    p.M = M; p.N = N; p.K = K;
    p.epi = epi; p.causalSkip = causalSkip; p.causalK = causalK; p.scale = scale;
    dim3 grid(N / 128, M / 128, batches);
    gemm_bf16x3<<<grid, 128, SMEM_BYTES>>>(p);
}

#define GETP(ptr, sym, T) T* ptr; { void* _p = 0; cudaGetSymbolAddress(&_p, sym); ptr = (T*)_p; }

extern "C" void kernel_launch(void* const* d_in, const int* in_sizes, int n_in,
                              void* d_out, int out_size) {
    const float* hs   = (const float*)d_in[0];
    const float* sinp = (const float*)d_in[1];
    const float* cosp = (const float*)d_in[2];
    const float* dm   = (const float*)d_in[3];
    const float* wq   = (const float*)d_in[4];
    const float* wk   = (const float*)d_in[5];
    const float* wv   = (const float*)d_in[6];
    const float* wg   = (const float*)d_in[7];
    const float* wo   = (const float*)d_in[8];
    float* out = (float*)d_out;

    cudaFuncSetAttribute(gemm_bf16x3, cudaFuncAttributeMaxDynamicSharedMemorySize, SMEM_BYTES);

    GETP(xhi,  g_xhi,  bf16)  GETP(xlo,  g_xlo,  bf16)
    GETP(wqhi, g_wqhi, bf16)  GETP(wqlo, g_wqlo, bf16)
    GETP(wkhi, g_wkhi, bf16)  GETP(wklo, g_wklo, bf16)
    GETP(wvhi, g_wvhi, bf16)  GETP(wvlo, g_wvlo, bf16)
    GETP(wghi, g_wghi, bf16)  GETP(wglo, g_wglo, bf16)
    GETP(wohi, g_wohi, bf16)  GETP(wolo, g_wolo, bf16)
    GETP(qrhi, g_qrhi, bf16)  GETP(qrlo, g_qrlo, bf16)
    GETP(krhi, g_krhi, bf16)  GETP(krlo, g_krlo, bf16)
    GETP(vthi, g_vthi, bf16)  GETP(vtlo, g_vtlo, bf16)
    GETP(gf,   g_gf,   float)
    GETP(shi,  g_shi,  bf16)  GETP(slo,  g_slo,  bf16)
    GETP(invp, g_invd, float)
    GETP(of,   g_of,   float)
    GETP(gahi, g_gahi, bf16)  GETP(galo, g_galo, bf16)

    // 1) ONE launch: split all fp32 inputs into bf16 hi/lo
    SplitArgs sa;
    sa.seg[0] = { hs, xhi,  xlo,  ((long)4096 * 2048) / 4 };
    sa.seg[1] = { wq, wqhi, wqlo, ((long)2048 * 2048) / 4 };
    sa.seg[2] = { wk, wkhi, wklo, ((long)2048 * 2048) / 4 };
    sa.seg[3] = { wv, wvhi, wvlo, ((long)4096 * 2048) / 4 };
    sa.seg[4] = { wg, wghi, wglo, ((long)4096 * 2048) / 4 };
    sa.seg[5] = { wo, wohi, wolo, ((long)2048 * 4096) / 4 };
    split_all_kernel<<<dim3(512, 6), 256>>>(sa);

    // 2) q/k projections with fused rotary (k scaled by 1/16) -> split qr/kr
    run_gemm(xhi, xlo, 2048, 0, 0, wqhi, wqlo, 2048, 0, 0,
             4096, 2048, 2048, 1, 4, 0, qrhi, qrlo, 2048, 0, 0,
             0, 0, sinp, cosp, 1.0f, 0, 0);
    run_gemm(xhi, xlo, 2048, 0, 0, wkhi, wklo, 2048, 0, 0,
             4096, 2048, 2048, 1, 4, 0, krhi, krlo, 2048, 0, 0,
             0, 0, sinp, cosp, 0.0625f, 0, 0);

    // 3) vT = Wv @ x^T per batch: (V, T)
    run_gemm(wvhi, wvlo, 2048, 0, 0, xhi, xlo, 2048, 0, (long)2048 * 2048,
             4096, 2048, 2048, 2, 1, 0, vthi, vtlo, 2048, 0, (long)4096 * 2048,
             0, 0, 0, 0, 1.0f, 0, 0);

    // 4) g projection -> fp32
    run_gemm(xhi, xlo, 2048, 0, 0, wghi, wglo, 2048, 0, 0,
             4096, 4096, 2048, 1, 0, gf, 0, 0, 4096, 0, 0,
             0, 0, 0, 0, 1.0f, 0, 0);

    // 5) S = (qr . kr^T) * dm, batched over 16 (b,h); skip strictly-upper tiles
    run_gemm(qrhi, qrlo, 2048, (long)2048 * 2048, 256,
             krhi, krlo, 2048, (long)2048 * 2048, 256,
             2048, 2048, 256, 16, 2, 0, shi, slo, 2048,
             (long)8 * 2048 * 2048, (long)2048 * 2048,
             dm, 0, 0, 0, 1.0f, 1, 0);

    // 6) inv = 1/max(|rowsum|,1)
    rowsum_kernel<<<dim3(2048, 16), 256>>>(shi, slo, invp);

    // 7) O = inv * (S @ vT^T), K causally limited; written as (b,t,h*HD+d)
    run_gemm(shi, slo, 2048, (long)8 * 2048 * 2048, (long)2048 * 2048,
             vthi, vtlo, 2048, (long)4096 * 2048, (long)512 * 2048,
             2048, 512, 2048, 16, 3, of, 0, 0, 4096,
             (long)2048 * 4096, 512,
             0, invp, 0, 0, 1.0f, 0, 1);

    // 8) per-head RMS norm + silu(g) gating -> split gated
    gate_kernel<<<32768, 128>>>(of, gf, gahi, galo);

    // 9) output projection -> d_out fp32
    run_gemm(gahi, galo, 4096, 0, 0, wohi, wolo, 4096, 0, 0,
             4096, 2048, 4096, 1, 0, out, 0, 0, 2048, 0, 0,
             0, 0, 0, 0, 1.0f, 0, 0);
}